// round 10
// baseline (speedup 1.0000x reference)
#include <cuda_runtime.h>
#include <cuda_fp16.h>
#include <math.h>
#include <stdint.h>

#define SQ    4096
#define HIDN  2048
#define NHEADS 16
#define NKVH   4
#define HDIM   128
#define QKVN  3072            // fused QKV output width
#define QOFF  0
#define KOFF  2048
#define VOFF  2560
#define KBLKS 64              // HIDN/32 k-tiles for GEMMs

// ---------------- scratch (static device globals; no allocation) ----------------
__device__ __half g_Xp [SQ * HIDN];        // X as fp16 A-fragments      16 MB
__device__ __half g_Wp [HIDN * QKVN];      // Wq|Wk|Wv fp16 B-fragments  12 MB
__device__ __half g_Wop[HIDN * HIDN];      // Wo fp16 B-fragments         8 MB
__device__ float  g_QKV[SQ * QKVN];        // fused QKV output (f32)     48 MB
__device__ __half g_Kh [NKVH * SQ * HDIM]; // rope'd K, fragment-packed   4 MB
__device__ __half g_Vh [NKVH * SQ * HDIM]; // V, fragment-packed          4 MB
__device__ __half g_AOp[SQ * HIDN];        // AO as fp16 A-frags (from attn) 16 MB

// ---------------- PTX helpers ----------------
__device__ __forceinline__ unsigned smem_u32(const void* p) {
    return (unsigned)__cvta_generic_to_shared(p);
}
__device__ __forceinline__ void cp_async16(unsigned dst, const void* src) {
    asm volatile("cp.async.cg.shared.global [%0], [%1], 16;\n" :: "r"(dst), "l"(src));
}
__device__ __forceinline__ void cp_commit() {
    asm volatile("cp.async.commit_group;\n");
}
template<int N> __device__ __forceinline__ void cp_wait() {
    asm volatile("cp.async.wait_group %0;\n" :: "n"(N));
}
__device__ __forceinline__ unsigned h2u(float lo, float hi) {
    __half2 h = __floats2half2_rn(lo, hi);
    return *(unsigned*)&h;
}
__device__ __forceinline__ void mma_f16(float& c0, float& c1, float& c2, float& c3,
                                        unsigned a0, unsigned a1, unsigned a2, unsigned a3,
                                        unsigned b0, unsigned b1) {
    asm volatile("mma.sync.aligned.m16n8k16.row.col.f32.f16.f16.f32 "
                 "{%0,%1,%2,%3},{%4,%5,%6,%7},{%8,%9},{%0,%1,%2,%3};"
                 : "+f"(c0), "+f"(c1), "+f"(c2), "+f"(c3)
                 : "r"(a0), "r"(a1), "r"(a2), "r"(a3), "r"(b0), "r"(b1));
}

// ============================================================================
// Pack kernels (fp16 mma fragments).
// A frag: [mblk][kblk][mt(8)][kt(2)][lane] 4 u32 (8 halves)
// B frag: [nblk][kblk][kt(2)][ng(16)][lane] 2 u32 (4 halves)
// ============================================================================
__global__ __launch_bounds__(256) void pack_A_h(const float* __restrict__ src,
                                                __half* __restrict__ dst, int K)
{
    const int KB = K >> 5;
    long long idx = (long long)blockIdx.x * 256 + threadIdx.x;
    int lane = (int)(idx & 31); long long f = idx >> 5;
    int kt = (int)(f & 1);  f >>= 1;
    int mt = (int)(f & 7);  f >>= 3;
    int kblk = (int)(f % KB);
    int mblk = (int)(f / KB);
    int g = lane >> 2, t = lane & 3;
    int r = mblk * 128 + mt * 16 + g;
    int c = kblk * 32 + kt * 16 + 2 * t;
    const float* p0 = src + (size_t)r * K + c;
    const float* p1 = src + (size_t)(r + 8) * K + c;
    uint4 v;
    v.x = h2u(p0[0], p0[1]);
    v.y = h2u(p1[0], p1[1]);
    v.z = h2u(p0[8], p0[9]);
    v.w = h2u(p1[8], p1[9]);
    ((uint4*)dst)[idx] = v;
}

__global__ __launch_bounds__(256) void pack_B_h(const float* __restrict__ src,
                                                __half* __restrict__ dst, int K, int N)
{
    const int KB = K >> 5;
    long long idx = (long long)blockIdx.x * 256 + threadIdx.x;
    int lane = (int)(idx & 31); long long f = idx >> 5;
    int ng = (int)(f & 15); f >>= 4;
    int kt = (int)(f & 1);  f >>= 1;
    int kblk = (int)(f % KB);
    int nblk = (int)(f / KB);
    int g = lane >> 2, t = lane & 3;
    int n = nblk * 128 + ng * 8 + g;
    int c = kblk * 32 + kt * 16 + 2 * t;
    uint2 v;
    v.x = h2u(src[(size_t)c * N + n],       src[(size_t)(c + 1) * N + n]);
    v.y = h2u(src[(size_t)(c + 8) * N + n], src[(size_t)(c + 9) * N + n]);
    ((uint2*)dst)[idx] = v;
}

// ============================================================================
// FP16 GEMM: C[M,N] = A @ B, pre-packed frags. 128x256 CTA tile, BK=32,
// 3-stage cp.async, 512 threads = 16 warps (4m x 4n, warp 32x64), ONE sync/iter.
// ============================================================================
#define GSTG 3
#define STAGE_H 12288                   // A 4096 + B(2 panels) 8192 halves = 24KB
#define GEMM_SMEM (GSTG * STAGE_H * 2)  // 73728 B

__global__ __launch_bounds__(512, 1) void gemm_h(
    const __half* __restrict__ Ap, const __half* __restrict__ Bp,
    float* __restrict__ C, int N, int KB)
{
    extern __shared__ __align__(16) __half shh[];
    const int tid  = threadIdx.x;
    const int lane = tid & 31, warp = tid >> 5;
    const int g = lane >> 2, t = lane & 3;
    const int wm = warp >> 2, wn = warp & 3;

    const __half* Abase = Ap + (size_t)blockIdx.y * KB * 4096;
    const __half* B0 = Bp + (size_t)(blockIdx.x * 2)     * KB * 4096;
    const __half* B1 = Bp + (size_t)(blockIdx.x * 2 + 1) * KB * 4096;

    float acc[2][8][4];
    #pragma unroll
    for (int i = 0; i < 2; i++)
        #pragma unroll
        for (int nt = 0; nt < 8; nt++)
            #pragma unroll
            for (int k = 0; k < 4; k++) acc[i][nt][k] = 0.0f;

    auto issue = [&](int it) {
        __half* st = shh + (it % GSTG) * STAGE_H;
        const __half* at = Abase + (size_t)it * 4096;
        const __half* b0 = B0 + (size_t)it * 4096;
        const __half* b1 = B1 + (size_t)it * 4096;
        #pragma unroll
        for (int j = 0; j < 3; j++) {
            int ch = tid + 512 * j;                    // 1536 x 16B chunks
            const __half* src = (ch < 512)  ? (at + ch * 8)
                              : (ch < 1024) ? (b0 + (ch - 512) * 8)
                                            : (b1 + (ch - 1024) * 8);
            cp_async16(smem_u32(st + ch * 8), src);
        }
    };

    issue(0); cp_commit();
    issue(1); cp_commit();

    for (int it = 0; it < KB; it++) {
        cp_wait<1>();
        __syncthreads();                 // stage it ready; all warps done with it-1
        if (it + 2 < KB) issue(it + 2);  // overwrites stage (it-1)%3 — safe
        cp_commit();

        const __half* st = shh + (it % GSTG) * STAGE_H;
        const uint4* af4 = (const uint4*)st;
        const uint2* bp  = (const uint2*)(st + ((wn < 2) ? 4096 : 8192));
        const int ngb = (wn & 1) * 8;

        #pragma unroll
        for (int kt = 0; kt < 2; kt++) {
            unsigned af[2][4], bf[8][2];
            #pragma unroll
            for (int i = 0; i < 2; i++) {
                int mt = wm * 2 + i;
                uint4 v = af4[(mt * 2 + kt) * 32 + lane];
                af[i][0] = v.x; af[i][1] = v.y; af[i][2] = v.z; af[i][3] = v.w;
            }
            #pragma unroll
            for (int nt = 0; nt < 8; nt++) {
                uint2 v = bp[(kt * 16 + ngb + nt) * 32 + lane];
                bf[nt][0] = v.x; bf[nt][1] = v.y;
            }
            #pragma unroll
            for (int i = 0; i < 2; i++)
                #pragma unroll
                for (int nt = 0; nt < 8; nt++)
                    mma_f16(acc[i][nt][0], acc[i][nt][1], acc[i][nt][2], acc[i][nt][3],
                            af[i][0], af[i][1], af[i][2], af[i][3],
                            bf[nt][0], bf[nt][1]);
        }
    }

    const int bm = blockIdx.y * 128, bn = blockIdx.x * 256;
    #pragma unroll
    for (int i = 0; i < 2; i++) {
        int row0 = bm + wm * 32 + i * 16 + g;
        #pragma unroll
        for (int nt = 0; nt < 8; nt++) {
            int col = bn + wn * 64 + nt * 8 + 2 * t;
            *(float2*)(C + (size_t)row0 * N + col)       = make_float2(acc[i][nt][0], acc[i][nt][1]);
            *(float2*)(C + (size_t)(row0 + 8) * N + col) = make_float2(acc[i][nt][2], acc[i][nt][3]);
        }
    }
}

// ============================================================================
// RoPE: Q in-place (f32); K (rope'd) / V written as fragment-packed fp16 tiles.
// ============================================================================
__device__ __forceinline__ void storeKfrag(__half* tile, int n, int dd, float v) {
    int ks = dd >> 4, r = dd & 15;
    int reg = r >> 3, t = (r & 7) >> 1, lo = r & 1;
    int lane = (n & 7) * 4 + t, nt = n >> 3;
    tile[(((ks * 8 + nt) * 32 + lane) << 2) + reg * 2 + lo] = __float2half_rn(v);
}
__device__ __forceinline__ void storeVfrag(__half* tile, int kk, int dd, float v) {
    int ks = kk >> 4, r = kk & 15;
    int reg = r >> 3, t = (r & 7) >> 1, lo = r & 1;
    int lane = (dd & 7) * 4 + t, nt = dd >> 3;
    tile[(((ks * 16 + nt) * 32 + lane) << 2) + reg * 2 + lo] = __float2half_rn(v);
}

__global__ void rope_kernel(float* __restrict__ QKV, __half* __restrict__ Kh,
                            __half* __restrict__ Vh, const int* __restrict__ pos_ids)
{
    __shared__ float s_inv[64];
    const int s = blockIdx.x;
    if (threadIdx.x < 64) {
        s_inv[threadIdx.x] =
            (float)exp2(-(double)threadIdx.x * (13.287712379549449 / 64.0));
    }
    __syncthreads();

    float* rowp = QKV + (size_t)s * QKVN;
    const float p = (float)pos_ids[s];
    const int kb = s >> 6, n = s & 63;

    for (int idx = threadIdx.x; idx < (NHEADS + NKVH) * 64; idx += blockDim.x) {
        if (idx < NHEADS * 64) {
            int h = idx >> 6, d = idx & 63;
            float* base = rowp + QOFF + h * HDIM;
            float ang = p * s_inv[d];
            float sn, cs;
            sincosf(ang, &sn, &cs);
            float x1 = base[d], x2 = base[d + 64];
            base[d]      = x1 * cs - x2 * sn;
            base[d + 64] = x2 * cs + x1 * sn;
        } else {
            int tt = idx - NHEADS * 64;
            int h = tt >> 6, d = tt & 63;
            const float* base = rowp + KOFF + h * HDIM;
            float ang = p * s_inv[d];
            float sn, cs;
            sincosf(ang, &sn, &cs);
            float x1 = base[d], x2 = base[d + 64];
            __half* tile = Kh + (size_t)(h * 64 + kb) * 8192;
            storeKfrag(tile, n, d,      x1 * cs - x2 * sn);
            storeKfrag(tile, n, d + 64, x2 * cs + x1 * sn);
        }
    }
    for (int idx = threadIdx.x; idx < NKVH * HDIM; idx += blockDim.x) {
        int h = idx >> 7, dd = idx & 127;
        __half* tile = Vh + (size_t)(h * 64 + kb) * 8192;
        storeVfrag(tile, n, dd, rowp[VOFF + idx]);
    }
}

// ============================================================================
// FP16 flash attention (f32 softmax/accum, causal, GQA 4:1).
// BQ=128 (8 warps x m16), BK=64, 3-stage KV ring, ONE sync/iter.
// Epilogue writes packed fp16 A-fragments of AO for the O-projection.
// ============================================================================
#define ATTN_SMEM (3 * 16384 * 2)   // 3 stages x (K 8192 + V 8192 halves) = 96KB

__global__ __launch_bounds__(256, 1) void attn_h(
    const float* __restrict__ QKV, const __half* __restrict__ Kh,
    const __half* __restrict__ Vh, __half* __restrict__ AOp)
{
    extern __shared__ __align__(16) __half shh[];
    const int tid = threadIdx.x, lane = tid & 31, warp = tid >> 5;
    const int g = lane >> 2, t = lane & 3;
    const int h = blockIdx.x;
    const int q = (int)(gridDim.y - 1 - blockIdx.y);   // heavy tiles first
    const int qbase = q * 128;
    const int kvh = h >> 2;
    const int niter = 2 * q + 2;
    // 1/sqrt(128) * log2(e): softmax done in exp2
    const float scale2 = 0.08838834764831845f * 1.4426950408889634f;

    unsigned qa[8][4];
    {
        const float* qp  = QKV + (size_t)(qbase + warp * 16 + g) * QKVN + QOFF + h * HDIM;
        const float* qp8 = qp + 8 * QKVN;
        #pragma unroll
        for (int ks = 0; ks < 8; ks++) {
            int c = ks * 16 + 2 * t;
            qa[ks][0] = h2u(scale2 * qp [c],     scale2 * qp [c + 1]);
            qa[ks][1] = h2u(scale2 * qp8[c],     scale2 * qp8[c + 1]);
            qa[ks][2] = h2u(scale2 * qp [c + 8], scale2 * qp [c + 9]);
            qa[ks][3] = h2u(scale2 * qp8[c + 8], scale2 * qp8[c + 9]);
        }
    }

    float oacc[16][4];
    #pragma unroll
    for (int nt = 0; nt < 16; nt++)
        #pragma unroll
        for (int i = 0; i < 4; i++) oacc[nt][i] = 0.0f;
    float m0 = -1e30f, m1 = -1e30f, l0 = 0.0f, l1 = 0.0f;

    auto issueKV = [&](int kb) {
        __half* st = shh + (kb % 3) * 16384;
        const __half* kg = Kh + (size_t)(kvh * 64 + kb) * 8192;
        const __half* vg = Vh + (size_t)(kvh * 64 + kb) * 8192;
        #pragma unroll
        for (int j = 0; j < 4; j++) {
            int ch = tid + 256 * j;                 // 1024 x 16B
            cp_async16(smem_u32(st + ch * 8), kg + ch * 8);
        }
        #pragma unroll
        for (int j = 0; j < 4; j++) {
            int ch = tid + 256 * j;
            cp_async16(smem_u32(st + 8192 + ch * 8), vg + ch * 8);
        }
    };
    issueKV(0); cp_commit();
    issueKV(1); cp_commit();

    for (int kb = 0; kb < niter; kb++) {
        cp_wait<1>();
        __syncthreads();                     // stage kb ready; all done with kb-1
        if (kb + 2 < niter) issueKV(kb + 2); // overwrites stage (kb-1)%3 — safe
        cp_commit();

        const uint2* kf = (const uint2*)(shh + (kb % 3) * 16384);
        const uint2* vf = (const uint2*)(shh + (kb % 3) * 16384 + 8192);

        float sacc[8][4];
        #pragma unroll
        for (int nt = 0; nt < 8; nt++)
            #pragma unroll
            for (int i = 0; i < 4; i++) sacc[nt][i] = 0.0f;

        #pragma unroll
        for (int ks = 0; ks < 8; ks++) {
            #pragma unroll
            for (int nt = 0; nt < 8; nt++) {
                uint2 b = kf[(ks * 8 + nt) * 32 + lane];
                mma_f16(sacc[nt][0], sacc[nt][1], sacc[nt][2], sacc[nt][3],
                        qa[ks][0], qa[ks][1], qa[ks][2], qa[ks][3], b.x, b.y);
            }
        }

        const int row0 = qbase + warp * 16 + g;
        if (kb >= niter - 2) {
            #pragma unroll
            for (int nt = 0; nt < 8; nt++) {
                int c0 = kb * 64 + nt * 8 + 2 * t;
                if (c0     > row0)     sacc[nt][0] = -1e30f;
                if (c0 + 1 > row0)     sacc[nt][1] = -1e30f;
                if (c0     > row0 + 8) sacc[nt][2] = -1e30f;
                if (c0 + 1 > row0 + 8) sacc[nt][3] = -1e30f;
            }
        }

        float mx0 = -1e30f, mx1 = -1e30f;
        #pragma unroll
        for (int nt = 0; nt < 8; nt++) {
            mx0 = fmaxf(mx0, fmaxf(sacc[nt][0], sacc[nt][1]));
            mx1 = fmaxf(mx1, fmaxf(sacc[nt][2], sacc[nt][3]));
        }
        mx0 = fmaxf(mx0, __shfl_xor_sync(0xffffffffu, mx0, 1));
        mx0 = fmaxf(mx0, __shfl_xor_sync(0xffffffffu, mx0, 2));
        mx1 = fmaxf(mx1, __shfl_xor_sync(0xffffffffu, mx1, 1));
        mx1 = fmaxf(mx1, __shfl_xor_sync(0xffffffffu, mx1, 2));

        float nm0 = fmaxf(m0, mx0), nm1 = fmaxf(m1, mx1);
        float al0 = exp2f(m0 - nm0), al1 = exp2f(m1 - nm1);
        float s0 = 0.0f, s1 = 0.0f;
        #pragma unroll
        for (int nt = 0; nt < 8; nt++) {
            sacc[nt][0] = exp2f(sacc[nt][0] - nm0); s0 += sacc[nt][0];
            sacc[nt][1] = exp2f(sacc[nt][1] - nm0); s0 += sacc[nt][1];
            sacc[nt][2] = exp2f(sacc[nt][2] - nm1); s1 += sacc[nt][2];
            sacc[nt][3] = exp2f(sacc[nt][3] - nm1); s1 += sacc[nt][3];
        }
        s0 += __shfl_xor_sync(0xffffffffu, s0, 1);
        s0 += __shfl_xor_sync(0xffffffffu, s0, 2);
        s1 += __shfl_xor_sync(0xffffffffu, s1, 1);
        s1 += __shfl_xor_sync(0xffffffffu, s1, 2);

        l0 = l0 * al0 + s0;  l1 = l1 * al1 + s1;
        m0 = nm0;            m1 = nm1;
        #pragma unroll
        for (int nt = 0; nt < 16; nt++) {
            oacc[nt][0] *= al0; oacc[nt][1] *= al0;
            oacc[nt][2] *= al1; oacc[nt][3] *= al1;
        }

        // ---- P fragments directly from S registers ----
        unsigned pa[4][4];
        #pragma unroll
        for (int ksp = 0; ksp < 4; ksp++) {
            pa[ksp][0] = h2u(sacc[2 * ksp][0],     sacc[2 * ksp][1]);
            pa[ksp][1] = h2u(sacc[2 * ksp][2],     sacc[2 * ksp][3]);
            pa[ksp][2] = h2u(sacc[2 * ksp + 1][0], sacc[2 * ksp + 1][1]);
            pa[ksp][3] = h2u(sacc[2 * ksp + 1][2], sacc[2 * ksp + 1][3]);
        }

        // ---- O += P @ V ----
        #pragma unroll
        for (int ksp = 0; ksp < 4; ksp++) {
            #pragma unroll
            for (int nt = 0; nt < 16; nt++) {
                uint2 b = vf[(ksp * 16 + nt) * 32 + lane];
                mma_f16(oacc[nt][0], oacc[nt][1], oacc[nt][2], oacc[nt][3],
                        pa[ksp][0], pa[ksp][1], pa[ksp][2], pa[ksp][3], b.x, b.y);
            }
        }
    }

    // ---- epilogue: normalize + emit packed fp16 A-fragments of AO ----
    // A-frag layout: [mblk=q][kblk][mt=warp][kt][lane] uint4; kblk = h*4+kb4.
    float i0 = 1.0f / l0, i1 = 1.0f / l1;
    uint4* dst = (uint4*)AOp;
    #pragma unroll
    for (int kb4 = 0; kb4 < 4; kb4++) {
        #pragma unroll
        for (int kt = 0; kt < 2; kt++) {
            int nt0 = kb4 * 4 + kt * 2;
            uint4 v;
            v.x = h2u(oacc[nt0][0] * i0,     oacc[nt0][1] * i0);
            v.y = h2u(oacc[nt0][2] * i1,     oacc[nt0][3] * i1);
            v.z = h2u(oacc[nt0 + 1][0] * i0, oacc[nt0 + 1][1] * i0);
            v.w = h2u(oacc[nt0 + 1][2] * i1, oacc[nt0 + 1][3] * i1);
            long long fi = (((long long)q * KBLKS + (h * 4 + kb4)) * 8 + warp) * 2 + kt;
            dst[fi * 32 + lane] = v;
        }
    }
}

// ============================================================================
// launch
// ============================================================================
extern "C" void kernel_launch(void* const* d_in, const int* in_sizes, int n_in,
                              void* d_out, int out_size)
{
    const float* X   = (const float*)d_in[0];
    const int*   pid = (const int*)  d_in[1];
    const float* Wq  = (const float*)d_in[2];
    const float* Wk  = (const float*)d_in[3];
    const float* Wv  = (const float*)d_in[4];
    const float* Wo  = (const float*)d_in[5];
    float* out = (float*)d_out;

    __half *Xp, *Wp, *Wop, *Kh, *Vh, *AOp;
    float *QKV;
    cudaGetSymbolAddress((void**)&Xp,  g_Xp);
    cudaGetSymbolAddress((void**)&Wp,  g_Wp);
    cudaGetSymbolAddress((void**)&Wop, g_Wop);
    cudaGetSymbolAddress((void**)&QKV, g_QKV);
    cudaGetSymbolAddress((void**)&Kh,  g_Kh);
    cudaGetSymbolAddress((void**)&Vh,  g_Vh);
    cudaGetSymbolAddress((void**)&AOp, g_AOp);

    cudaFuncSetAttribute(gemm_h,
                         cudaFuncAttributeMaxDynamicSharedMemorySize, GEMM_SMEM);
    cudaFuncSetAttribute(attn_h,
                         cudaFuncAttributeMaxDynamicSharedMemorySize, ATTN_SMEM);

    // ---- pack operands to fp16 fragments ----
    pack_A_h<<<(SQ * HIDN / 8) / 256, 256>>>(X, Xp, HIDN);
    pack_B_h<<<(HIDN * HIDN / 4) / 256, 256>>>(Wq, Wp, HIDN, HIDN);                       // panels 0-15
    pack_B_h<<<(HIDN * 512  / 4) / 256, 256>>>(Wk, Wp + (size_t)16 * KBLKS * 4096, HIDN, 512);
    pack_B_h<<<(HIDN * 512  / 4) / 256, 256>>>(Wv, Wp + (size_t)20 * KBLKS * 4096, HIDN, 512);
    pack_B_h<<<(HIDN * HIDN / 4) / 256, 256>>>(Wo, Wop, HIDN, HIDN);

    // ---- fused QKV projection (128x256 tiles) ----
    gemm_h<<<dim3(QKVN / 256, SQ / 128), 512, GEMM_SMEM>>>(Xp, Wp, QKV, QKVN, KBLKS);

    // ---- RoPE + K/V fragment packing ----
    rope_kernel<<<SQ, 256>>>(QKV, Kh, Vh, pid);

    // ---- attention (writes packed AO fragments) ----
    dim3 ga(NHEADS, SQ / 128);
    attn_h<<<ga, 256, ATTN_SMEM>>>(QKV, Kh, Vh, AOp);

    // ---- output projection ----
    gemm_h<<<dim3(HIDN / 256, SQ / 128), 512, GEMM_SMEM>>>(AOp, Wop, out, HIDN, KBLKS);
}

// round 13
// speedup vs baseline: 1.0609x; 1.0609x over previous
#include <cuda_runtime.h>
#include <cuda_fp16.h>
#include <math.h>
#include <stdint.h>

#define SQ    4096
#define HIDN  2048
#define NHEADS 16
#define NKVH   4
#define HDIM   128
#define QKVN  3072            // fused QKV output width
#define QOFF  0
#define KOFF  2048
#define VOFF  2560
#define KBLKS 64              // HIDN/32 k-tiles for GEMMs

// ---------------- scratch (static device globals; no allocation) ----------------
__device__ __half g_Xp [SQ * HIDN];        // X as fp16 A-fragments      16 MB
__device__ __half g_Wp [HIDN * QKVN];      // Wq|Wk|Wv fp16 B-fragments  12 MB
__device__ __half g_Wop[HIDN * HIDN];      // Wo fp16 B-fragments         8 MB
__device__ float  g_QKV[SQ * QKVN];        // fused QKV output (f32)     48 MB
__device__ __half g_Kh [NKVH * SQ * HDIM]; // rope'd K, fragment-packed   4 MB
__device__ __half g_Vh [NKVH * SQ * HDIM]; // V, fragment-packed          4 MB
__device__ __half g_AOp[SQ * HIDN];        // AO as fp16 A-frags (from attn) 16 MB

// ---------------- PTX helpers ----------------
__device__ __forceinline__ unsigned smem_u32(const void* p) {
    return (unsigned)__cvta_generic_to_shared(p);
}
__device__ __forceinline__ void cp_async16(unsigned dst, const void* src) {
    asm volatile("cp.async.cg.shared.global [%0], [%1], 16;\n" :: "r"(dst), "l"(src));
}
__device__ __forceinline__ void cp_commit() {
    asm volatile("cp.async.commit_group;\n");
}
template<int N> __device__ __forceinline__ void cp_wait() {
    asm volatile("cp.async.wait_group %0;\n" :: "n"(N));
}
__device__ __forceinline__ unsigned h2u(float lo, float hi) {
    __half2 h = __floats2half2_rn(lo, hi);
    return *(unsigned*)&h;
}
__device__ __forceinline__ void mma_f16(float& c0, float& c1, float& c2, float& c3,
                                        unsigned a0, unsigned a1, unsigned a2, unsigned a3,
                                        unsigned b0, unsigned b1) {
    asm volatile("mma.sync.aligned.m16n8k16.row.col.f32.f16.f16.f32 "
                 "{%0,%1,%2,%3},{%4,%5,%6,%7},{%8,%9},{%0,%1,%2,%3};"
                 : "+f"(c0), "+f"(c1), "+f"(c2), "+f"(c3)
                 : "r"(a0), "r"(a1), "r"(a2), "r"(a3), "r"(b0), "r"(b1));
}

// ============================================================================
// Pack kernels (fp16 mma fragments).
// A frag: [mblk][kblk][mt(8)][kt(2)][lane] 4 u32 (8 halves)
// B frag: [nblk][kblk][kt(2)][ng(16)][lane] 2 u32 (4 halves)
// ============================================================================
__global__ __launch_bounds__(256) void pack_A_h(const float* __restrict__ src,
                                                __half* __restrict__ dst, int K)
{
    const int KB = K >> 5;
    long long idx = (long long)blockIdx.x * 256 + threadIdx.x;
    int lane = (int)(idx & 31); long long f = idx >> 5;
    int kt = (int)(f & 1);  f >>= 1;
    int mt = (int)(f & 7);  f >>= 3;
    int kblk = (int)(f % KB);
    int mblk = (int)(f / KB);
    int g = lane >> 2, t = lane & 3;
    int r = mblk * 128 + mt * 16 + g;
    int c = kblk * 32 + kt * 16 + 2 * t;
    const float* p0 = src + (size_t)r * K + c;
    const float* p1 = src + (size_t)(r + 8) * K + c;
    uint4 v;
    v.x = h2u(p0[0], p0[1]);
    v.y = h2u(p1[0], p1[1]);
    v.z = h2u(p0[8], p0[9]);
    v.w = h2u(p1[8], p1[9]);
    ((uint4*)dst)[idx] = v;
}

__global__ __launch_bounds__(256) void pack_B_h(const float* __restrict__ src,
                                                __half* __restrict__ dst, int K, int N)
{
    const int KB = K >> 5;
    long long idx = (long long)blockIdx.x * 256 + threadIdx.x;
    int lane = (int)(idx & 31); long long f = idx >> 5;
    int ng = (int)(f & 15); f >>= 4;
    int kt = (int)(f & 1);  f >>= 1;
    int kblk = (int)(f % KB);
    int nblk = (int)(f / KB);
    int g = lane >> 2, t = lane & 3;
    int n = nblk * 128 + ng * 8 + g;
    int c = kblk * 32 + kt * 16 + 2 * t;
    uint2 v;
    v.x = h2u(src[(size_t)c * N + n],       src[(size_t)(c + 1) * N + n]);
    v.y = h2u(src[(size_t)(c + 8) * N + n], src[(size_t)(c + 9) * N + n]);
    ((uint2*)dst)[idx] = v;
}

// ============================================================================
// FP16 GEMM (R9 measured-good config): C[M,N] = A @ B, pre-packed fragments.
// 128x128 CTA, BK=32, 3-stage cp.async, 256 threads = 8 warps (2m x 4n),
// 2 CTAs/SM.
// ============================================================================
#define GSTG 3
#define STAGE_H 8192                    // A 4096 + B 4096 halves = 16KB
#define GEMM_SMEM (GSTG * STAGE_H * 2)  // 49152 B

__global__ __launch_bounds__(256, 2) void gemm_h(
    const __half* __restrict__ Ap, const __half* __restrict__ Bp,
    float* __restrict__ C, int N, int KB)
{
    extern __shared__ __align__(16) __half shh[];
    const int tid  = threadIdx.x;
    const int lane = tid & 31, warp = tid >> 5;
    const int g = lane >> 2, t = lane & 3;
    const int wm = warp >> 2, wn = warp & 3;

    const __half* Abase = Ap + (size_t)blockIdx.y * KB * 4096;
    const __half* Bbase = Bp + (size_t)blockIdx.x * KB * 4096;

    float acc[4][4][4];
    #pragma unroll
    for (int mt = 0; mt < 4; mt++)
        #pragma unroll
        for (int nt = 0; nt < 4; nt++)
            #pragma unroll
            for (int i = 0; i < 4; i++) acc[mt][nt][i] = 0.0f;

    auto issue = [&](int it) {
        __half* st = shh + (it % GSTG) * STAGE_H;
        const __half* at = Abase + (size_t)it * 4096;
        const __half* bt = Bbase + (size_t)it * 4096;
        #pragma unroll
        for (int j = 0; j < 4; j++) {
            int ch = tid + 256 * j;                       // 1024 x 16B
            const __half* src = (ch < 512) ? (at + ch * 8) : (bt + (ch - 512) * 8);
            cp_async16(smem_u32(st + ch * 8), src);
        }
    };

    issue(0); cp_commit();
    issue(1); cp_commit();

    for (int it = 0; it < KB; it++) {
        cp_wait<1>();
        __syncthreads();
        if (it + 2 < KB) issue(it + 2);
        cp_commit();

        const __half* st = shh + (it % GSTG) * STAGE_H;
        const uint4* af4 = (const uint4*)st;
        const uint2* bf2 = (const uint2*)(st + 4096);

        #pragma unroll
        for (int kt = 0; kt < 2; kt++) {
            unsigned af[4][4], bf[4][2];
            #pragma unroll
            for (int i = 0; i < 4; i++) {
                int mt = wm * 4 + i;
                uint4 v = af4[(mt * 2 + kt) * 32 + lane];
                af[i][0] = v.x; af[i][1] = v.y; af[i][2] = v.z; af[i][3] = v.w;
            }
            #pragma unroll
            for (int nt = 0; nt < 4; nt++) {
                int ng = wn * 4 + nt;
                uint2 v = bf2[(kt * 16 + ng) * 32 + lane];
                bf[nt][0] = v.x; bf[nt][1] = v.y;
            }
            #pragma unroll
            for (int mt = 0; mt < 4; mt++)
                #pragma unroll
                for (int nt = 0; nt < 4; nt++)
                    mma_f16(acc[mt][nt][0], acc[mt][nt][1], acc[mt][nt][2], acc[mt][nt][3],
                            af[mt][0], af[mt][1], af[mt][2], af[mt][3],
                            bf[nt][0], bf[nt][1]);
        }
        __syncthreads();
    }

    const int bm = blockIdx.y * 128, bn = blockIdx.x * 128;
    #pragma unroll
    for (int mt = 0; mt < 4; mt++) {
        int row0 = bm + wm * 64 + mt * 16 + g;
        #pragma unroll
        for (int nt = 0; nt < 4; nt++) {
            int col = bn + wn * 32 + nt * 8 + 2 * t;
            *(float2*)(C + (size_t)row0 * N + col)       = make_float2(acc[mt][nt][0], acc[mt][nt][1]);
            *(float2*)(C + (size_t)(row0 + 8) * N + col) = make_float2(acc[mt][nt][2], acc[mt][nt][3]);
        }
    }
}

// ============================================================================
// RoPE: Q in-place (f32); K (rope'd) / V written as fragment-packed fp16 tiles.
// ============================================================================
__device__ __forceinline__ void storeKfrag(__half* tile, int n, int dd, float v) {
    int ks = dd >> 4, r = dd & 15;
    int reg = r >> 3, t = (r & 7) >> 1, lo = r & 1;
    int lane = (n & 7) * 4 + t, nt = n >> 3;
    tile[(((ks * 8 + nt) * 32 + lane) << 2) + reg * 2 + lo] = __float2half_rn(v);
}
__device__ __forceinline__ void storeVfrag(__half* tile, int kk, int dd, float v) {
    int ks = kk >> 4, r = kk & 15;
    int reg = r >> 3, t = (r & 7) >> 1, lo = r & 1;
    int lane = (dd & 7) * 4 + t, nt = dd >> 3;
    tile[(((ks * 16 + nt) * 32 + lane) << 2) + reg * 2 + lo] = __float2half_rn(v);
}

__global__ void rope_kernel(float* __restrict__ QKV, __half* __restrict__ Kh,
                            __half* __restrict__ Vh, const int* __restrict__ pos_ids)
{
    __shared__ float s_inv[64];
    const int s = blockIdx.x;
    if (threadIdx.x < 64) {
        s_inv[threadIdx.x] =
            (float)exp2(-(double)threadIdx.x * (13.287712379549449 / 64.0));
    }
    __syncthreads();

    float* rowp = QKV + (size_t)s * QKVN;
    const float p = (float)pos_ids[s];
    const int kb = s >> 6, n = s & 63;

    for (int idx = threadIdx.x; idx < (NHEADS + NKVH) * 64; idx += blockDim.x) {
        if (idx < NHEADS * 64) {
            int h = idx >> 6, d = idx & 63;
            float* base = rowp + QOFF + h * HDIM;
            float ang = p * s_inv[d];
            float sn, cs;
            sincosf(ang, &sn, &cs);
            float x1 = base[d], x2 = base[d + 64];
            base[d]      = x1 * cs - x2 * sn;
            base[d + 64] = x2 * cs + x1 * sn;
        } else {
            int tt = idx - NHEADS * 64;
            int h = tt >> 6, d = tt & 63;
            const float* base = rowp + KOFF + h * HDIM;
            float ang = p * s_inv[d];
            float sn, cs;
            sincosf(ang, &sn, &cs);
            float x1 = base[d], x2 = base[d + 64];
            __half* tile = Kh + (size_t)(h * 64 + kb) * 8192;
            storeKfrag(tile, n, d,      x1 * cs - x2 * sn);
            storeKfrag(tile, n, d + 64, x2 * cs + x1 * sn);
        }
    }
    for (int idx = threadIdx.x; idx < NKVH * HDIM; idx += blockDim.x) {
        int h = idx >> 7, dd = idx & 127;
        __half* tile = Vh + (size_t)(h * 64 + kb) * 8192;
        storeVfrag(tile, n, dd, rowp[VOFF + idx]);
    }
}

// ============================================================================
// FP16 flash attention (f32 softmax/accum, causal, GQA 4:1).
// BQ=128 (8 warps x m16), BK=64, 3-stage KV ring, one sync/iter.
// Epilogue writes packed fp16 A-fragments of AO for the O-projection.
// ============================================================================
#define ATTN_SMEM (3 * 16384 * 2)   // 3 stages x (K 8192 + V 8192 halves) = 96KB

__global__ __launch_bounds__(256, 1) void attn_h(
    const float* __restrict__ QKV, const __half* __restrict__ Kh,
    const __half* __restrict__ Vh, __half* __restrict__ AOp)
{
    extern __shared__ __align__(16) __half shh[];
    const int tid = threadIdx.x, lane = tid & 31, warp = tid >> 5;
    const int g = lane >> 2, t = lane & 3;
    const int h = blockIdx.x;
    const int q = (int)(gridDim.y - 1 - blockIdx.y);   // heavy tiles first
    const int qbase = q * 128;
    const int kvh = h >> 2;
    const int niter = 2 * q + 2;
    // 1/sqrt(128) * log2(e): softmax done in exp2
    const float scale2 = 0.08838834764831845f * 1.4426950408889634f;

    unsigned qa[8][4];
    {
        const float* qp  = QKV + (size_t)(qbase + warp * 16 + g) * QKVN + QOFF + h * HDIM;
        const float* qp8 = qp + 8 * QKVN;
        #pragma unroll
        for (int ks = 0; ks < 8; ks++) {
            int c = ks * 16 + 2 * t;
            qa[ks][0] = h2u(scale2 * qp [c],     scale2 * qp [c + 1]);
            qa[ks][1] = h2u(scale2 * qp8[c],     scale2 * qp8[c + 1]);
            qa[ks][2] = h2u(scale2 * qp [c + 8], scale2 * qp [c + 9]);
            qa[ks][3] = h2u(scale2 * qp8[c + 8], scale2 * qp8[c + 9]);
        }
    }

    float oacc[16][4];
    #pragma unroll
    for (int nt = 0; nt < 16; nt++)
        #pragma unroll
        for (int i = 0; i < 4; i++) oacc[nt][i] = 0.0f;
    float m0 = -1e30f, m1 = -1e30f, l0 = 0.0f, l1 = 0.0f;

    auto issueKV = [&](int kb) {
        __half* st = shh + (kb % 3) * 16384;
        const __half* kg = Kh + (size_t)(kvh * 64 + kb) * 8192;
        const __half* vg = Vh + (size_t)(kvh * 64 + kb) * 8192;
        #pragma unroll
        for (int j = 0; j < 4; j++) {
            int ch = tid + 256 * j;                 // 1024 x 16B
            cp_async16(smem_u32(st + ch * 8), kg + ch * 8);
        }
        #pragma unroll
        for (int j = 0; j < 4; j++) {
            int ch = tid + 256 * j;
            cp_async16(smem_u32(st + 8192 + ch * 8), vg + ch * 8);
        }
    };
    issueKV(0); cp_commit();
    issueKV(1); cp_commit();

    for (int kb = 0; kb < niter; kb++) {
        cp_wait<1>();
        __syncthreads();                     // stage kb ready; all done with kb-1
        if (kb + 2 < niter) issueKV(kb + 2); // overwrites stage (kb-1)%3 — safe
        cp_commit();

        const uint2* kf = (const uint2*)(shh + (kb % 3) * 16384);
        const uint2* vf = (const uint2*)(shh + (kb % 3) * 16384 + 8192);

        float sacc[8][4];
        #pragma unroll
        for (int nt = 0; nt < 8; nt++)
            #pragma unroll
            for (int i = 0; i < 4; i++) sacc[nt][i] = 0.0f;

        #pragma unroll
        for (int ks = 0; ks < 8; ks++) {
            #pragma unroll
            for (int nt = 0; nt < 8; nt++) {
                uint2 b = kf[(ks * 8 + nt) * 32 + lane];
                mma_f16(sacc[nt][0], sacc[nt][1], sacc[nt][2], sacc[nt][3],
                        qa[ks][0], qa[ks][1], qa[ks][2], qa[ks][3], b.x, b.y);
            }
        }

        const int row0 = qbase + warp * 16 + g;
        if (kb >= niter - 2) {
            #pragma unroll
            for (int nt = 0; nt < 8; nt++) {
                int c0 = kb * 64 + nt * 8 + 2 * t;
                if (c0     > row0)     sacc[nt][0] = -1e30f;
                if (c0 + 1 > row0)     sacc[nt][1] = -1e30f;
                if (c0     > row0 + 8) sacc[nt][2] = -1e30f;
                if (c0 + 1 > row0 + 8) sacc[nt][3] = -1e30f;
            }
        }

        float mx0 = -1e30f, mx1 = -1e30f;
        #pragma unroll
        for (int nt = 0; nt < 8; nt++) {
            mx0 = fmaxf(mx0, fmaxf(sacc[nt][0], sacc[nt][1]));
            mx1 = fmaxf(mx1, fmaxf(sacc[nt][2], sacc[nt][3]));
        }
        mx0 = fmaxf(mx0, __shfl_xor_sync(0xffffffffu, mx0, 1));
        mx0 = fmaxf(mx0, __shfl_xor_sync(0xffffffffu, mx0, 2));
        mx1 = fmaxf(mx1, __shfl_xor_sync(0xffffffffu, mx1, 1));
        mx1 = fmaxf(mx1, __shfl_xor_sync(0xffffffffu, mx1, 2));

        float nm0 = fmaxf(m0, mx0), nm1 = fmaxf(m1, mx1);
        float al0 = exp2f(m0 - nm0), al1 = exp2f(m1 - nm1);
        float s0 = 0.0f, s1 = 0.0f;
        #pragma unroll
        for (int nt = 0; nt < 8; nt++) {
            sacc[nt][0] = exp2f(sacc[nt][0] - nm0); s0 += sacc[nt][0];
            sacc[nt][1] = exp2f(sacc[nt][1] - nm0); s0 += sacc[nt][1];
            sacc[nt][2] = exp2f(sacc[nt][2] - nm1); s1 += sacc[nt][2];
            sacc[nt][3] = exp2f(sacc[nt][3] - nm1); s1 += sacc[nt][3];
        }
        s0 += __shfl_xor_sync(0xffffffffu, s0, 1);
        s0 += __shfl_xor_sync(0xffffffffu, s0, 2);
        s1 += __shfl_xor_sync(0xffffffffu, s1, 1);
        s1 += __shfl_xor_sync(0xffffffffu, s1, 2);

        l0 = l0 * al0 + s0;  l1 = l1 * al1 + s1;
        m0 = nm0;            m1 = nm1;
        #pragma unroll
        for (int nt = 0; nt < 16; nt++) {
            oacc[nt][0] *= al0; oacc[nt][1] *= al0;
            oacc[nt][2] *= al1; oacc[nt][3] *= al1;
        }

        // ---- P fragments directly from S registers ----
        unsigned pa[4][4];
        #pragma unroll
        for (int ksp = 0; ksp < 4; ksp++) {
            pa[ksp][0] = h2u(sacc[2 * ksp][0],     sacc[2 * ksp][1]);
            pa[ksp][1] = h2u(sacc[2 * ksp][2],     sacc[2 * ksp][3]);
            pa[ksp][2] = h2u(sacc[2 * ksp + 1][0], sacc[2 * ksp + 1][1]);
            pa[ksp][3] = h2u(sacc[2 * ksp + 1][2], sacc[2 * ksp + 1][3]);
        }

        // ---- O += P @ V ----
        #pragma unroll
        for (int ksp = 0; ksp < 4; ksp++) {
            #pragma unroll
            for (int nt = 0; nt < 16; nt++) {
                uint2 b = vf[(ksp * 16 + nt) * 32 + lane];
                mma_f16(oacc[nt][0], oacc[nt][1], oacc[nt][2], oacc[nt][3],
                        pa[ksp][0], pa[ksp][1], pa[ksp][2], pa[ksp][3], b.x, b.y);
            }
        }
    }

    // ---- epilogue: normalize + emit packed fp16 A-fragments of AO ----
    // A-frag layout: [mblk=q][kblk][mt=warp][kt][lane] uint4; kblk = h*4+kb4.
    float i0 = 1.0f / l0, i1 = 1.0f / l1;
    uint4* dst = (uint4*)AOp;
    #pragma unroll
    for (int kb4 = 0; kb4 < 4; kb4++) {
        #pragma unroll
        for (int kt = 0; kt < 2; kt++) {
            int nt0 = kb4 * 4 + kt * 2;
            uint4 v;
            v.x = h2u(oacc[nt0][0] * i0,     oacc[nt0][1] * i0);
            v.y = h2u(oacc[nt0][2] * i1,     oacc[nt0][3] * i1);
            v.z = h2u(oacc[nt0 + 1][0] * i0, oacc[nt0 + 1][1] * i0);
            v.w = h2u(oacc[nt0 + 1][2] * i1, oacc[nt0 + 1][3] * i1);
            long long fi = (((long long)q * KBLKS + (h * 4 + kb4)) * 8 + warp) * 2 + kt;
            dst[fi * 32 + lane] = v;
        }
    }
}

// ============================================================================
// launch
// ============================================================================
extern "C" void kernel_launch(void* const* d_in, const int* in_sizes, int n_in,
                              void* d_out, int out_size)
{
    const float* X   = (const float*)d_in[0];
    const int*   pid = (const int*)  d_in[1];
    const float* Wq  = (const float*)d_in[2];
    const float* Wk  = (const float*)d_in[3];
    const float* Wv  = (const float*)d_in[4];
    const float* Wo  = (const float*)d_in[5];
    float* out = (float*)d_out;

    __half *Xp, *Wp, *Wop, *Kh, *Vh, *AOp;
    float *QKV;
    cudaGetSymbolAddress((void**)&Xp,  g_Xp);
    cudaGetSymbolAddress((void**)&Wp,  g_Wp);
    cudaGetSymbolAddress((void**)&Wop, g_Wop);
    cudaGetSymbolAddress((void**)&QKV, g_QKV);
    cudaGetSymbolAddress((void**)&Kh,  g_Kh);
    cudaGetSymbolAddress((void**)&Vh,  g_Vh);
    cudaGetSymbolAddress((void**)&AOp, g_AOp);

    cudaFuncSetAttribute(gemm_h,
                         cudaFuncAttributeMaxDynamicSharedMemorySize, GEMM_SMEM);
    cudaFuncSetAttribute(attn_h,
                         cudaFuncAttributeMaxDynamicSharedMemorySize, ATTN_SMEM);

    // ---- pack operands to fp16 fragments ----
    pack_A_h<<<(SQ * HIDN / 8) / 256, 256>>>(X, Xp, HIDN);
    pack_B_h<<<(HIDN * HIDN / 4) / 256, 256>>>(Wq, Wp, HIDN, HIDN);                       // panels 0-15
    pack_B_h<<<(HIDN * 512  / 4) / 256, 256>>>(Wk, Wp + (size_t)16 * KBLKS * 4096, HIDN, 512);
    pack_B_h<<<(HIDN * 512  / 4) / 256, 256>>>(Wv, Wp + (size_t)20 * KBLKS * 4096, HIDN, 512);
    pack_B_h<<<(HIDN * HIDN / 4) / 256, 256>>>(Wo, Wop, HIDN, HIDN);

    // ---- fused QKV projection (128x128 tiles, 2 CTAs/SM) ----
    gemm_h<<<dim3(QKVN / 128, SQ / 128), 256, GEMM_SMEM>>>(Xp, Wp, QKV, QKVN, KBLKS);

    // ---- RoPE + K/V fragment packing ----
    rope_kernel<<<SQ, 256>>>(QKV, Kh, Vh, pid);

    // ---- attention (writes packed AO fragments) ----
    dim3 ga(NHEADS, SQ / 128);
    attn_h<<<ga, 256, ATTN_SMEM>>>(QKV, Kh, Vh, AOp);

    // ---- output projection ----
    gemm_h<<<dim3(HIDN / 128, SQ / 128), 256, GEMM_SMEM>>>(AOp, Wop, out, HIDN, KBLKS);
}

// round 16
// speedup vs baseline: 1.0924x; 1.0297x over previous
#include <cuda_runtime.h>
#include <cuda_fp16.h>
#include <math.h>
#include <stdint.h>

#define SQ    4096
#define HIDN  2048
#define NHEADS 16
#define NKVH   4
#define HDIM   128
#define QKVN  3072            // fused QKV output width
#define QOFF  0
#define KOFF  2048
#define VOFF  2560
#define KBLKS 64              // HIDN/32 k-tiles for GEMMs

// ---------------- scratch (static device globals; no allocation) ----------------
__device__ __half g_Xp [SQ * HIDN];        // X as fp16 A-fragments      16 MB
__device__ __half g_Wp [HIDN * QKVN];      // Wq|Wk|Wv fp16 B-fragments  12 MB
__device__ __half g_Wop[HIDN * HIDN];      // Wo fp16 B-fragments         8 MB
__device__ float  g_QKV[SQ * QKVN];        // fused QKV output (f32)     48 MB
__device__ __half g_Kh [NKVH * SQ * HDIM]; // rope'd K, fragment-packed   4 MB
__device__ __half g_Vh [NKVH * SQ * HDIM]; // V, fragment-packed          4 MB
__device__ __half g_AOp[SQ * HIDN];        // AO as fp16 A-frags (from attn) 16 MB

// ---------------- PTX helpers ----------------
__device__ __forceinline__ unsigned smem_u32(const void* p) {
    return (unsigned)__cvta_generic_to_shared(p);
}
__device__ __forceinline__ void cp_async16(unsigned dst, const void* src) {
    asm volatile("cp.async.cg.shared.global [%0], [%1], 16;\n" :: "r"(dst), "l"(src));
}
__device__ __forceinline__ void cp_commit() {
    asm volatile("cp.async.commit_group;\n");
}
template<int N> __device__ __forceinline__ void cp_wait() {
    asm volatile("cp.async.wait_group %0;\n" :: "n"(N));
}
__device__ __forceinline__ unsigned h2u(float lo, float hi) {
    __half2 h = __floats2half2_rn(lo, hi);
    return *(unsigned*)&h;
}
__device__ __forceinline__ void mma_f16(float& c0, float& c1, float& c2, float& c3,
                                        unsigned a0, unsigned a1, unsigned a2, unsigned a3,
                                        unsigned b0, unsigned b1) {
    asm volatile("mma.sync.aligned.m16n8k16.row.col.f32.f16.f16.f32 "
                 "{%0,%1,%2,%3},{%4,%5,%6,%7},{%8,%9},{%0,%1,%2,%3};"
                 : "+f"(c0), "+f"(c1), "+f"(c2), "+f"(c3)
                 : "r"(a0), "r"(a1), "r"(a2), "r"(a3), "r"(b0), "r"(b1));
}

// ============================================================================
// Fused coalesced pack kernel: X + Wq + Wk + Wv + Wo in ONE launch.
// Output layouts IDENTICAL to the old pack_A_h / pack_B_h:
//  A frag: [(mblk*64+kblk)*512 + (mt*2+kt)*32 + lane] uint4
//    v.x={A[r][c],A[r][c+1]} v.y={A[r+8][c],..} v.z={A[r][c+8],A[r][c+9]} v.w={A[r+8][c+8],..}
//    r=mblk*128+mt*16+g, c=kblk*32+kt*16+2t
//  B frag: [pan*1024 + (kt*16+ng)*32 + lane] uint2
//    v.x={B[c][n],B[c+1][n]} v.y={B[c+8][n],B[c+9][n]}
//    c=kblk*32+kt*16+2t, n=nblk*128+ng*8+g
// Each CTA stages one tile through smem: coalesced float4 global reads,
// coalesced fragment writes.
// ============================================================================
#define PACK_X_TILES  (32 * 64)   // 2048
#define PACK_WQ_TILES (16 * 64)   // 1024
#define PACK_WK_TILES (4 * 64)    // 256
#define PACK_WV_TILES (4 * 64)    // 256
#define PACK_WO_TILES (16 * 64)   // 1024
#define PACK_TILES (PACK_X_TILES + PACK_WQ_TILES + PACK_WK_TILES + PACK_WV_TILES + PACK_WO_TILES)

__global__ __launch_bounds__(256) void pack_all(
    const float* __restrict__ X,  const float* __restrict__ Wq,
    const float* __restrict__ Wk, const float* __restrict__ Wv,
    const float* __restrict__ Wo,
    __half* __restrict__ Xp, __half* __restrict__ Wp, __half* __restrict__ Wop)
{
    __shared__ float sm[4608];     // A: 128 rows x stride 36; B: 32 rows x stride 132
    const int bid = blockIdx.x;
    const int tid = threadIdx.x;

    if (bid < PACK_X_TILES) {
        // ---- A-pack: 128(m) x 32(k) tile of X ----
        int mblk = bid >> 6, kblk = bid & 63;
        const float* src = X + (size_t)(mblk * 128) * HIDN + kblk * 32;
        #pragma unroll
        for (int j = 0; j < 4; j++) {
            int e = tid + 256 * j;                 // 1024 float4 (8 per row)
            int row = e >> 3, c4 = e & 7;
            float4 v = *(const float4*)(src + (size_t)row * HIDN + c4 * 4);
            *(float4*)(sm + row * 36 + c4 * 4) = v;
        }
        __syncthreads();
        uint4* dst = (uint4*)Xp + (size_t)bid * 512;
        #pragma unroll
        for (int j = 0; j < 2; j++) {
            int f = tid + 256 * j;                 // 512 uint4
            int lane = f & 31, fg = f >> 5;        // fg = mt*2+kt
            int kt = fg & 1, mt = fg >> 1;
            int g = lane >> 2, t = lane & 3;
            int r = mt * 16 + g, c = kt * 16 + 2 * t;
            uint4 v;
            v.x = h2u(sm[r * 36 + c],           sm[r * 36 + c + 1]);
            v.y = h2u(sm[(r + 8) * 36 + c],     sm[(r + 8) * 36 + c + 1]);
            v.z = h2u(sm[r * 36 + c + 8],       sm[r * 36 + c + 9]);
            v.w = h2u(sm[(r + 8) * 36 + c + 8], sm[(r + 8) * 36 + c + 9]);
            dst[f] = v;
        }
    } else {
        // ---- B-pack: 32(k) x 128(n) tile of a weight matrix ----
        const float* src;
        __half* dstbase;
        int N, nblk, kblk, pan;
        int id = bid - PACK_X_TILES;
        if (id < PACK_WQ_TILES) {
            src = Wq; N = HIDN; nblk = id >> 6; kblk = id & 63;
            dstbase = Wp;  pan = nblk * 64 + kblk;
        } else if ((id -= PACK_WQ_TILES) < PACK_WK_TILES) {
            src = Wk; N = 512;  nblk = id >> 6; kblk = id & 63;
            dstbase = Wp;  pan = (16 + nblk) * 64 + kblk;
        } else if ((id -= PACK_WK_TILES) < PACK_WV_TILES) {
            src = Wv; N = 512;  nblk = id >> 6; kblk = id & 63;
            dstbase = Wp;  pan = (20 + nblk) * 64 + kblk;
        } else {
            id -= PACK_WV_TILES;
            src = Wo; N = HIDN; nblk = id >> 6; kblk = id & 63;
            dstbase = Wop; pan = nblk * 64 + kblk;
        }
        const float* s0 = src + (size_t)(kblk * 32) * N + nblk * 128;
        #pragma unroll
        for (int j = 0; j < 4; j++) {
            int e = tid + 256 * j;                 // 1024 float4 (32 per row)
            int row = e >> 5, c4 = e & 31;
            float4 v = *(const float4*)(s0 + (size_t)row * N + c4 * 4);
            *(float4*)(sm + row * 132 + c4 * 4) = v;
        }
        __syncthreads();
        uint2* dst = (uint2*)dstbase + (size_t)pan * 1024;
        #pragma unroll
        for (int j = 0; j < 4; j++) {
            int f = tid + 256 * j;                 // 1024 uint2
            int lane = f & 31, fg = f >> 5;        // fg = kt*16+ng
            int kt = fg >> 4, ng = fg & 15;
            int g = lane >> 2, t = lane & 3;
            int nl = ng * 8 + g, cl = kt * 16 + 2 * t;
            uint2 v;
            v.x = h2u(sm[cl * 132 + nl],       sm[(cl + 1) * 132 + nl]);
            v.y = h2u(sm[(cl + 8) * 132 + nl], sm[(cl + 9) * 132 + nl]);
            dst[f] = v;
        }
    }
}

// ============================================================================
// FP16 GEMM (measured-good config): C[M,N] = A @ B, pre-packed fragments.
// 128x128 CTA, BK=32, 3-stage cp.async, 256 threads = 8 warps (2m x 4n),
// 2 CTAs/SM.
// ============================================================================
#define GSTG 3
#define STAGE_H 8192                    // A 4096 + B 4096 halves = 16KB
#define GEMM_SMEM (GSTG * STAGE_H * 2)  // 49152 B

__global__ __launch_bounds__(256, 2) void gemm_h(
    const __half* __restrict__ Ap, const __half* __restrict__ Bp,
    float* __restrict__ C, int N, int KB)
{
    extern __shared__ __align__(16) __half shh[];
    const int tid  = threadIdx.x;
    const int lane = tid & 31, warp = tid >> 5;
    const int g = lane >> 2, t = lane & 3;
    const int wm = warp >> 2, wn = warp & 3;

    const __half* Abase = Ap + (size_t)blockIdx.y * KB * 4096;
    const __half* Bbase = Bp + (size_t)blockIdx.x * KB * 4096;

    float acc[4][4][4];
    #pragma unroll
    for (int mt = 0; mt < 4; mt++)
        #pragma unroll
        for (int nt = 0; nt < 4; nt++)
            #pragma unroll
            for (int i = 0; i < 4; i++) acc[mt][nt][i] = 0.0f;

    auto issue = [&](int it) {
        __half* st = shh + (it % GSTG) * STAGE_H;
        const __half* at = Abase + (size_t)it * 4096;
        const __half* bt = Bbase + (size_t)it * 4096;
        #pragma unroll
        for (int j = 0; j < 4; j++) {
            int ch = tid + 256 * j;                       // 1024 x 16B
            const __half* src = (ch < 512) ? (at + ch * 8) : (bt + (ch - 512) * 8);
            cp_async16(smem_u32(st + ch * 8), src);
        }
    };

    issue(0); cp_commit();
    issue(1); cp_commit();

    for (int it = 0; it < KB; it++) {
        cp_wait<1>();
        __syncthreads();
        if (it + 2 < KB) issue(it + 2);
        cp_commit();

        const __half* st = shh + (it % GSTG) * STAGE_H;
        const uint4* af4 = (const uint4*)st;
        const uint2* bf2 = (const uint2*)(st + 4096);

        #pragma unroll
        for (int kt = 0; kt < 2; kt++) {
            unsigned af[4][4], bf[4][2];
            #pragma unroll
            for (int i = 0; i < 4; i++) {
                int mt = wm * 4 + i;
                uint4 v = af4[(mt * 2 + kt) * 32 + lane];
                af[i][0] = v.x; af[i][1] = v.y; af[i][2] = v.z; af[i][3] = v.w;
            }
            #pragma unroll
            for (int nt = 0; nt < 4; nt++) {
                int ng = wn * 4 + nt;
                uint2 v = bf2[(kt * 16 + ng) * 32 + lane];
                bf[nt][0] = v.x; bf[nt][1] = v.y;
            }
            #pragma unroll
            for (int mt = 0; mt < 4; mt++)
                #pragma unroll
                for (int nt = 0; nt < 4; nt++)
                    mma_f16(acc[mt][nt][0], acc[mt][nt][1], acc[mt][nt][2], acc[mt][nt][3],
                            af[mt][0], af[mt][1], af[mt][2], af[mt][3],
                            bf[nt][0], bf[nt][1]);
        }
        __syncthreads();
    }

    const int bm = blockIdx.y * 128, bn = blockIdx.x * 128;
    #pragma unroll
    for (int mt = 0; mt < 4; mt++) {
        int row0 = bm + wm * 64 + mt * 16 + g;
        #pragma unroll
        for (int nt = 0; nt < 4; nt++) {
            int col = bn + wn * 32 + nt * 8 + 2 * t;
            *(float2*)(C + (size_t)row0 * N + col)       = make_float2(acc[mt][nt][0], acc[mt][nt][1]);
            *(float2*)(C + (size_t)(row0 + 8) * N + col) = make_float2(acc[mt][nt][2], acc[mt][nt][3]);
        }
    }
}

// ============================================================================
// RoPE: Q in-place (f32); K (rope'd) / V written as fragment-packed fp16 tiles.
// ============================================================================
__device__ __forceinline__ void storeKfrag(__half* tile, int n, int dd, float v) {
    int ks = dd >> 4, r = dd & 15;
    int reg = r >> 3, t = (r & 7) >> 1, lo = r & 1;
    int lane = (n & 7) * 4 + t, nt = n >> 3;
    tile[(((ks * 8 + nt) * 32 + lane) << 2) + reg * 2 + lo] = __float2half_rn(v);
}
__device__ __forceinline__ void storeVfrag(__half* tile, int kk, int dd, float v) {
    int ks = kk >> 4, r = kk & 15;
    int reg = r >> 3, t = (r & 7) >> 1, lo = r & 1;
    int lane = (dd & 7) * 4 + t, nt = dd >> 3;
    tile[(((ks * 16 + nt) * 32 + lane) << 2) + reg * 2 + lo] = __float2half_rn(v);
}

__global__ void rope_kernel(float* __restrict__ QKV, __half* __restrict__ Kh,
                            __half* __restrict__ Vh, const int* __restrict__ pos_ids)
{
    __shared__ float s_inv[64];
    const int s = blockIdx.x;
    if (threadIdx.x < 64) {
        s_inv[threadIdx.x] =
            (float)exp2(-(double)threadIdx.x * (13.287712379549449 / 64.0));
    }
    __syncthreads();

    float* rowp = QKV + (size_t)s * QKVN;
    const float p = (float)pos_ids[s];
    const int kb = s >> 6, n = s & 63;

    for (int idx = threadIdx.x; idx < (NHEADS + NKVH) * 64; idx += blockDim.x) {
        if (idx < NHEADS * 64) {
            int h = idx >> 6, d = idx & 63;
            float* base = rowp + QOFF + h * HDIM;
            float ang = p * s_inv[d];
            float sn, cs;
            sincosf(ang, &sn, &cs);
            float x1 = base[d], x2 = base[d + 64];
            base[d]      = x1 * cs - x2 * sn;
            base[d + 64] = x2 * cs + x1 * sn;
        } else {
            int tt = idx - NHEADS * 64;
            int h = tt >> 6, d = tt & 63;
            const float* base = rowp + KOFF + h * HDIM;
            float ang = p * s_inv[d];
            float sn, cs;
            sincosf(ang, &sn, &cs);
            float x1 = base[d], x2 = base[d + 64];
            __half* tile = Kh + (size_t)(h * 64 + kb) * 8192;
            storeKfrag(tile, n, d,      x1 * cs - x2 * sn);
            storeKfrag(tile, n, d + 64, x2 * cs + x1 * sn);
        }
    }
    for (int idx = threadIdx.x; idx < NKVH * HDIM; idx += blockDim.x) {
        int h = idx >> 7, dd = idx & 127;
        __half* tile = Vh + (size_t)(h * 64 + kb) * 8192;
        storeVfrag(tile, n, dd, rowp[VOFF + idx]);
    }
}

// ============================================================================
// FP16 flash attention (f32 softmax/accum, causal, GQA 4:1).
// BQ=128 (8 warps x m16), BK=64, 3-stage KV ring, one sync/iter.
// Epilogue writes packed fp16 A-fragments of AO for the O-projection.
// ============================================================================
#define ATTN_SMEM (3 * 16384 * 2)   // 3 stages x (K 8192 + V 8192 halves) = 96KB

__global__ __launch_bounds__(256, 1) void attn_h(
    const float* __restrict__ QKV, const __half* __restrict__ Kh,
    const __half* __restrict__ Vh, __half* __restrict__ AOp)
{
    extern __shared__ __align__(16) __half shh[];
    const int tid = threadIdx.x, lane = tid & 31, warp = tid >> 5;
    const int g = lane >> 2, t = lane & 3;
    const int h = blockIdx.x;
    const int q = (int)(gridDim.y - 1 - blockIdx.y);   // heavy tiles first
    const int qbase = q * 128;
    const int kvh = h >> 2;
    const int niter = 2 * q + 2;
    // 1/sqrt(128) * log2(e): softmax done in exp2
    const float scale2 = 0.08838834764831845f * 1.4426950408889634f;

    unsigned qa[8][4];
    {
        const float* qp  = QKV + (size_t)(qbase + warp * 16 + g) * QKVN + QOFF + h * HDIM;
        const float* qp8 = qp + 8 * QKVN;
        #pragma unroll
        for (int ks = 0; ks < 8; ks++) {
            int c = ks * 16 + 2 * t;
            qa[ks][0] = h2u(scale2 * qp [c],     scale2 * qp [c + 1]);
            qa[ks][1] = h2u(scale2 * qp8[c],     scale2 * qp8[c + 1]);
            qa[ks][2] = h2u(scale2 * qp [c + 8], scale2 * qp [c + 9]);
            qa[ks][3] = h2u(scale2 * qp8[c + 8], scale2 * qp8[c + 9]);
        }
    }

    float oacc[16][4];
    #pragma unroll
    for (int nt = 0; nt < 16; nt++)
        #pragma unroll
        for (int i = 0; i < 4; i++) oacc[nt][i] = 0.0f;
    float m0 = -1e30f, m1 = -1e30f, l0 = 0.0f, l1 = 0.0f;

    auto issueKV = [&](int kb) {
        __half* st = shh + (kb % 3) * 16384;
        const __half* kg = Kh + (size_t)(kvh * 64 + kb) * 8192;
        const __half* vg = Vh + (size_t)(kvh * 64 + kb) * 8192;
        #pragma unroll
        for (int j = 0; j < 4; j++) {
            int ch = tid + 256 * j;                 // 1024 x 16B
            cp_async16(smem_u32(st + ch * 8), kg + ch * 8);
        }
        #pragma unroll
        for (int j = 0; j < 4; j++) {
            int ch = tid + 256 * j;
            cp_async16(smem_u32(st + 8192 + ch * 8), vg + ch * 8);
        }
    };
    issueKV(0); cp_commit();
    issueKV(1); cp_commit();

    for (int kb = 0; kb < niter; kb++) {
        cp_wait<1>();
        __syncthreads();                     // stage kb ready; all done with kb-1
        if (kb + 2 < niter) issueKV(kb + 2); // overwrites stage (kb-1)%3 — safe
        cp_commit();

        const uint2* kf = (const uint2*)(shh + (kb % 3) * 16384);
        const uint2* vf = (const uint2*)(shh + (kb % 3) * 16384 + 8192);

        float sacc[8][4];
        #pragma unroll
        for (int nt = 0; nt < 8; nt++)
            #pragma unroll
            for (int i = 0; i < 4; i++) sacc[nt][i] = 0.0f;

        #pragma unroll
        for (int ks = 0; ks < 8; ks++) {
            #pragma unroll
            for (int nt = 0; nt < 8; nt++) {
                uint2 b = kf[(ks * 8 + nt) * 32 + lane];
                mma_f16(sacc[nt][0], sacc[nt][1], sacc[nt][2], sacc[nt][3],
                        qa[ks][0], qa[ks][1], qa[ks][2], qa[ks][3], b.x, b.y);
            }
        }

        const int row0 = qbase + warp * 16 + g;
        if (kb >= niter - 2) {
            #pragma unroll
            for (int nt = 0; nt < 8; nt++) {
                int c0 = kb * 64 + nt * 8 + 2 * t;
                if (c0     > row0)     sacc[nt][0] = -1e30f;
                if (c0 + 1 > row0)     sacc[nt][1] = -1e30f;
                if (c0     > row0 + 8) sacc[nt][2] = -1e30f;
                if (c0 + 1 > row0 + 8) sacc[nt][3] = -1e30f;
            }
        }

        float mx0 = -1e30f, mx1 = -1e30f;
        #pragma unroll
        for (int nt = 0; nt < 8; nt++) {
            mx0 = fmaxf(mx0, fmaxf(sacc[nt][0], sacc[nt][1]));
            mx1 = fmaxf(mx1, fmaxf(sacc[nt][2], sacc[nt][3]));
        }
        mx0 = fmaxf(mx0, __shfl_xor_sync(0xffffffffu, mx0, 1));
        mx0 = fmaxf(mx0, __shfl_xor_sync(0xffffffffu, mx0, 2));
        mx1 = fmaxf(mx1, __shfl_xor_sync(0xffffffffu, mx1, 1));
        mx1 = fmaxf(mx1, __shfl_xor_sync(0xffffffffu, mx1, 2));

        float nm0 = fmaxf(m0, mx0), nm1 = fmaxf(m1, mx1);
        float al0 = exp2f(m0 - nm0), al1 = exp2f(m1 - nm1);
        float s0 = 0.0f, s1 = 0.0f;
        #pragma unroll
        for (int nt = 0; nt < 8; nt++) {
            sacc[nt][0] = exp2f(sacc[nt][0] - nm0); s0 += sacc[nt][0];
            sacc[nt][1] = exp2f(sacc[nt][1] - nm0); s0 += sacc[nt][1];
            sacc[nt][2] = exp2f(sacc[nt][2] - nm1); s1 += sacc[nt][2];
            sacc[nt][3] = exp2f(sacc[nt][3] - nm1); s1 += sacc[nt][3];
        }
        s0 += __shfl_xor_sync(0xffffffffu, s0, 1);
        s0 += __shfl_xor_sync(0xffffffffu, s0, 2);
        s1 += __shfl_xor_sync(0xffffffffu, s1, 1);
        s1 += __shfl_xor_sync(0xffffffffu, s1, 2);

        l0 = l0 * al0 + s0;  l1 = l1 * al1 + s1;
        m0 = nm0;            m1 = nm1;
        #pragma unroll
        for (int nt = 0; nt < 16; nt++) {
            oacc[nt][0] *= al0; oacc[nt][1] *= al0;
            oacc[nt][2] *= al1; oacc[nt][3] *= al1;
        }

        // ---- P fragments directly from S registers ----
        unsigned pa[4][4];
        #pragma unroll
        for (int ksp = 0; ksp < 4; ksp++) {
            pa[ksp][0] = h2u(sacc[2 * ksp][0],     sacc[2 * ksp][1]);
            pa[ksp][1] = h2u(sacc[2 * ksp][2],     sacc[2 * ksp][3]);
            pa[ksp][2] = h2u(sacc[2 * ksp + 1][0], sacc[2 * ksp + 1][1]);
            pa[ksp][3] = h2u(sacc[2 * ksp + 1][2], sacc[2 * ksp + 1][3]);
        }

        // ---- O += P @ V ----
        #pragma unroll
        for (int ksp = 0; ksp < 4; ksp++) {
            #pragma unroll
            for (int nt = 0; nt < 16; nt++) {
                uint2 b = vf[(ksp * 16 + nt) * 32 + lane];
                mma_f16(oacc[nt][0], oacc[nt][1], oacc[nt][2], oacc[nt][3],
                        pa[ksp][0], pa[ksp][1], pa[ksp][2], pa[ksp][3], b.x, b.y);
            }
        }
    }

    // ---- epilogue: normalize + emit packed fp16 A-fragments of AO ----
    // A-frag layout: [mblk=q][kblk][mt=warp][kt][lane] uint4; kblk = h*4+kb4.
    float i0 = 1.0f / l0, i1 = 1.0f / l1;
    uint4* dst = (uint4*)AOp;
    #pragma unroll
    for (int kb4 = 0; kb4 < 4; kb4++) {
        #pragma unroll
        for (int kt = 0; kt < 2; kt++) {
            int nt0 = kb4 * 4 + kt * 2;
            uint4 v;
            v.x = h2u(oacc[nt0][0] * i0,     oacc[nt0][1] * i0);
            v.y = h2u(oacc[nt0][2] * i1,     oacc[nt0][3] * i1);
            v.z = h2u(oacc[nt0 + 1][0] * i0, oacc[nt0 + 1][1] * i0);
            v.w = h2u(oacc[nt0 + 1][2] * i1, oacc[nt0 + 1][3] * i1);
            long long fi = (((long long)q * KBLKS + (h * 4 + kb4)) * 8 + warp) * 2 + kt;
            dst[fi * 32 + lane] = v;
        }
    }
}

// ============================================================================
// launch
// ============================================================================
extern "C" void kernel_launch(void* const* d_in, const int* in_sizes, int n_in,
                              void* d_out, int out_size)
{
    const float* X   = (const float*)d_in[0];
    const int*   pid = (const int*)  d_in[1];
    const float* Wq  = (const float*)d_in[2];
    const float* Wk  = (const float*)d_in[3];
    const float* Wv  = (const float*)d_in[4];
    const float* Wo  = (const float*)d_in[5];
    float* out = (float*)d_out;

    __half *Xp, *Wp, *Wop, *Kh, *Vh, *AOp;
    float *QKV;
    cudaGetSymbolAddress((void**)&Xp,  g_Xp);
    cudaGetSymbolAddress((void**)&Wp,  g_Wp);
    cudaGetSymbolAddress((void**)&Wop, g_Wop);
    cudaGetSymbolAddress((void**)&QKV, g_QKV);
    cudaGetSymbolAddress((void**)&Kh,  g_Kh);
    cudaGetSymbolAddress((void**)&Vh,  g_Vh);
    cudaGetSymbolAddress((void**)&AOp, g_AOp);

    cudaFuncSetAttribute(gemm_h,
                         cudaFuncAttributeMaxDynamicSharedMemorySize, GEMM_SMEM);
    cudaFuncSetAttribute(attn_h,
                         cudaFuncAttributeMaxDynamicSharedMemorySize, ATTN_SMEM);

    // ---- one fused, coalesced pack launch (X + all weights) ----
    pack_all<<<PACK_TILES, 256>>>(X, Wq, Wk, Wv, Wo, Xp, Wp, Wop);

    // ---- fused QKV projection (128x128 tiles, 2 CTAs/SM) ----
    gemm_h<<<dim3(QKVN / 128, SQ / 128), 256, GEMM_SMEM>>>(Xp, Wp, QKV, QKVN, KBLKS);

    // ---- RoPE + K/V fragment packing ----
    rope_kernel<<<SQ, 256>>>(QKV, Kh, Vh, pid);

    // ---- attention (writes packed AO fragments) ----
    dim3 ga(NHEADS, SQ / 128);
    attn_h<<<ga, 256, ATTN_SMEM>>>(QKV, Kh, Vh, AOp);

    // ---- output projection ----
    gemm_h<<<dim3(HIDN / 128, SQ / 128), 256, GEMM_SMEM>>>(AOp, Wop, out, HIDN, KBLKS);
}